// round 6
// baseline (speedup 1.0000x reference)
#include <cuda_runtime.h>
#include <math.h>
#include <stdint.h>

#define M_MAX   360448
#define NMAX    8100000
#define PD      614
#define MAXV    1024
#define QFPS    410
#define MAXPTS  32
#define CAP     128
#define LCAP    8192
#define HBINS   2048
#define NB      148
#define NT      256
#define CPT     10      // NB*NT*CPT = 378880 >= M_MAX

__device__ int                g_count[M_MAX];
__device__ int                g_keys[NMAX];
__device__ int                g_newindex[M_MAX];
__device__ unsigned char      g_valid[M_MAX];
__device__ int                g_hist[HBINS];
__device__ int                g_T;
__device__ unsigned int       g_list[LCAP];
__device__ int                g_listn;
__device__ int                g_sel[MAXV];
__device__ int                g_start;
__device__ unsigned long long g_part[2][NB];
__device__ unsigned int       g_bar;
__device__ int                g_ctr[MAXV];
__device__ int                g_buf[MAXV * CAP];

struct P9 { float lox, loy, loz, vx, vy, vz; int gx, gy, gz, M; };

__device__ __forceinline__ P9 mkp(const float* vs, const float* cr) {
    P9 p;
    p.lox = cr[0]; p.loy = cr[1]; p.loz = cr[2];
    p.vx = vs[0]; p.vy = vs[1]; p.vz = vs[2];
    p.gx = (int)floorf(__fdiv_rn(__fsub_rn(cr[3], cr[0]), vs[0]));
    p.gy = (int)floorf(__fdiv_rn(__fsub_rn(cr[4], cr[1]), vs[1]));
    p.gz = (int)floorf(__fdiv_rn(__fsub_rn(cr[5], cr[2]), vs[2]));
    p.M = p.gx * p.gy * p.gz;
    return p;
}

// centroid: STRICT separate mul + add (locked by R1-R4 evidence)
__device__ __forceinline__ void decode_centroid(int key, const P9& p,
                                                float& cx, float& cy, float& cz) {
    int gyz = p.gy * p.gz;
    int ix = key / gyz;
    int r  = key - ix * gyz;
    int iy = r / p.gz;
    int iz = r - iy * p.gz;
    cx = __fadd_rn(__fmul_rn((float)ix, p.vx), p.lox);
    cy = __fadd_rn(__fmul_rn((float)iy, p.vy), p.loy);
    cz = __fadd_rn(__fmul_rn((float)iz, p.vz), p.loz);
}

// ---------------- reset ----------------
__global__ void k_reset() {
    int i = blockIdx.x * blockDim.x + threadIdx.x;
    if (i < M_MAX) { g_count[i] = 0; g_newindex[i] = -1; }
    if (i < HBINS) g_hist[i] = 0;
    if (i < LCAP)  g_list[i] = 0xFFFFFFFFu;
    if (i < MAXV)  g_ctr[i] = 0;
    if (i == 0) { g_bar = 0u; g_listn = 0; g_start = 0x7FFFFFFF; g_T = 1; }
}

// ---------------- pass 1: keys + histogram ----------------
__global__ void k_points(const float* __restrict__ pts, const float* vs,
                         const float* cr, int N) {
    int i = blockIdx.x * blockDim.x + threadIdx.x;
    if (i >= N || i >= NMAX) return;
    P9 p = mkp(vs, cr);
    float x = pts[3 * i + 0];
    float y = pts[3 * i + 1];
    float z = pts[3 * i + 2];
    int vxi = (int)floorf(__fdiv_rn(__fsub_rn(x, p.lox), p.vx));
    int vyi = (int)floorf(__fdiv_rn(__fsub_rn(y, p.loy), p.vy));
    int vzi = (int)floorf(__fdiv_rn(__fsub_rn(z, p.loz), p.vz));
    vxi = min(max(vxi, 0), p.gx - 1);
    vyi = min(max(vyi, 0), p.gy - 1);
    vzi = min(max(vzi, 0), p.gz - 1);
    int key = (vxi * p.gy + vyi) * p.gz + vzi;
    g_keys[i] = key;
    atomicAdd(&g_count[key], 1);
}

// ---------------- count histogram ----------------
__global__ void k_hist(const float* vs, const float* cr) {
    int k = blockIdx.x * blockDim.x + threadIdx.x;
    P9 p = mkp(vs, cr);
    if (k >= p.M) return;
    int c = g_count[k];
    if (c > 0) atomicAdd(&g_hist[min(c, HBINS - 1)], 1);
}

// ---------------- threshold T: 614th largest count ----------------
__global__ void k_thresh() {
    int acc = 0;
    for (int c = HBINS - 1; c >= 1; c--) {
        acc += g_hist[c];
        if (acc >= PD) { g_T = c; return; }
    }
    g_T = 1;
}

// ---------------- collect keys with count >= T ----------------
__global__ void k_collect(const float* vs, const float* cr) {
    int k = blockIdx.x * blockDim.x + threadIdx.x;
    P9 p = mkp(vs, cr);
    if (k >= p.M) return;
    int c = g_count[k];
    if (c >= g_T) {
        int pos = atomicAdd(&g_listn, 1);
        if (pos < LCAP) {
            unsigned cc = (unsigned)min(c, HBINS - 1);
            g_list[pos] = (((unsigned)(HBINS - 1) - cc) << 19) | (unsigned)k;
        }
    }
}

// ---------------- sort candidates, take top PD in (count desc, key asc) ----------------
__global__ void k_sorttop() {
    __shared__ unsigned int s[LCAP];
    int tid = threadIdx.x;
    for (int t = tid; t < LCAP; t += blockDim.x) s[t] = g_list[t];
    __syncthreads();
    for (int ks = 2; ks <= LCAP; ks <<= 1) {
        for (int j = ks >> 1; j > 0; j >>= 1) {
            for (int t = tid; t < LCAP; t += blockDim.x) {
                int ixj = t ^ j;
                if (ixj > t) {
                    bool up = ((t & ks) == 0);
                    unsigned a = s[t], b = s[ixj];
                    if ((a > b) == up) { s[t] = b; s[ixj] = a; }
                }
            }
            __syncthreads();
        }
    }
    if (tid < PD) {
        int key = (int)(s[tid] & 0x7FFFFu);
        g_sel[tid] = key;
        g_newindex[key] = tid;
    }
}

// ---------------- FPS validity mask + start (smallest remaining key) ----------------
__global__ void k_prep(const float* vs, const float* cr) {
    int k = blockIdx.x * blockDim.x + threadIdx.x;
    P9 p = mkp(vs, cr);
    if (k >= p.M) return;
    int v = (g_count[k] > 0 && g_newindex[k] < 0) ? 1 : 0;
    g_valid[k] = (unsigned char)v;
    if (v) atomicMin(&g_start, k);
}

__global__ void k_startk() { g_sel[PD] = g_start; }

// ---------------- persistent FPS kernel: 409 steps, 1 grid barrier each ----------------
__global__ __launch_bounds__(NT) void k_fps(const float* vs, const float* cr) {
    P9 p = mkp(vs, cr);
    int tid = threadIdx.x, b = blockIdx.x;
    int base = b * (NT * CPT);

    float dist[CPT], cx[CPT], cy[CPT], cz[CPT];
    unsigned vm = 0;
#pragma unroll
    for (int j = 0; j < CPT; j++) {
        int k = base + j * NT + tid;
        float X = 0.f, Y = 0.f, Z = 0.f;
        int ok = 0;
        if (k < p.M) {
            ok = g_valid[k];
            decode_centroid(k, p, X, Y, Z);
        }
        cx[j] = X; cy[j] = Y; cz[j] = Z;
        dist[j] = __int_as_float(0x7f800000);  // +inf
        vm |= (ok ? 1u : 0u) << j;
    }

    __shared__ unsigned long long sred[NT / 32];
    __shared__ int s_last;
    int last = g_sel[PD];
    unsigned int target = 0;

    for (int s = 0; s < QFPS - 1; s++) {
        float lx, ly, lz;
        decode_centroid(last, p, lx, ly, lz);

        unsigned long long best = 0ull;
#pragma unroll
        for (int j = 0; j < CPT; j++) {
            float dx = __fsub_rn(cx[j], lx);
            float dy = __fsub_rn(cy[j], ly);
            float dz = __fsub_rn(cz[j], lz);
            // variant F (LLVM LHS-first contraction):
            //   add(dx2, dy2)  -> fma(dx,dx, rn(dy*dy))
            //   add(prev, dz2) -> fma(dz,dz, prev)
            float d = __fmaf_rn(dz, dz, __fmaf_rn(dx, dx, __fmul_rn(dy, dy)));
            float nd = fminf(dist[j], d);
            dist[j] = nd;
            if ((vm >> j) & 1u) {
                int k = base + j * NT + tid;
                unsigned long long pk =
                    ((unsigned long long)__float_as_uint(nd) << 32) |
                    (unsigned long long)(0xFFFFFFFFu - (unsigned)k);
                best = max(best, pk);
            }
        }
        // block reduce (max)
        for (int o = 16; o; o >>= 1)
            best = max(best, __shfl_xor_sync(0xFFFFFFFFu, best, o));
        if ((tid & 31) == 0) sred[tid >> 5] = best;
        __syncthreads();
        if (tid < 32) {
            unsigned long long v = (tid < NT / 32) ? sred[tid] : 0ull;
            for (int o = 4; o; o >>= 1)
                v = max(v, __shfl_xor_sync(0xFFFFFFFFu, v, o));
            if (tid == 0) {
                g_part[s & 1][b] = v;
                __threadfence();
                atomicAdd(&g_bar, 1u);
            }
        }
        target += NB;
        if (tid == 0) {
            volatile unsigned int* bp = &g_bar;
            while (*bp < target) { }
            __threadfence();
        }
        __syncthreads();

        // every block redundantly reduces the NB partials (no 2nd barrier)
        unsigned long long v = 0ull;
        if (tid < NB)
            v = *((volatile unsigned long long*)&g_part[s & 1][tid]);
        for (int o = 16; o; o >>= 1)
            v = max(v, __shfl_xor_sync(0xFFFFFFFFu, v, o));
        if ((tid & 31) == 0) sred[tid >> 5] = v;
        __syncthreads();
        if (tid == 0) {
            unsigned long long m = sred[0];
            for (int w = 1; w < NT / 32; w++) m = max(m, sred[w]);
            int nk = (int)(0xFFFFFFFFu - (unsigned)(m & 0xFFFFFFFFull));
            s_last = nk;
            if (b == 0) g_sel[PD + 1 + s] = nk;
        }
        __syncthreads();
        last = s_last;
    }
}

// ---------------- finalize slots: new_index, coords, nums ----------------
__global__ void k_final(const float* vs, const float* cr, float* out, int out_size) {
    int j = blockIdx.x * blockDim.x + threadIdx.x;
    if (j >= MAXV) return;
    P9 p = mkp(vs, cr);
    int key = g_sel[j];
    g_newindex[key] = j;
    int gyz = p.gy * p.gz;
    int ix = key / gyz;
    int r  = key - ix * gyz;
    int iy = r / p.gz;
    int iz = r - iy * p.gz;
    int cbase = MAXV * MAXPTS * 3;
    if (out_size >= cbase + MAXV * 3) {
        out[cbase + 3 * j + 0] = (float)ix;
        out[cbase + 3 * j + 1] = (float)iy;
        out[cbase + 3 * j + 2] = (float)iz;
    }
    int nbase = cbase + MAXV * 3;
    if (out_size >= nbase + MAXV)
        out[nbase + j] = (float)min(g_count[key], MAXPTS);
}

// ---------------- pass 2: collect point indices of selected voxels ----------------
__global__ void k_cpts(int N) {
    int i = blockIdx.x * blockDim.x + threadIdx.x;
    if (i >= N || i >= NMAX) return;
    int k = g_keys[i];
    int s = g_newindex[k];
    if (s >= 0) {
        int pos = atomicAdd(&g_ctr[s], 1);
        if (pos < CAP) g_buf[s * CAP + pos] = i;
    }
}

// ---------------- per-slot: sort indices, emit first min(count,32) points ----------------
__global__ void k_emit(const float* __restrict__ pts, float* out) {
    __shared__ int sb[CAP];
    int s = blockIdx.x, t = threadIdx.x;
    int m = min(g_ctr[s], CAP);
    sb[t] = (t < m) ? g_buf[s * CAP + t] : 0x7FFFFFFF;
    __syncthreads();
    for (int ks = 2; ks <= CAP; ks <<= 1) {
        for (int j = ks >> 1; j > 0; j >>= 1) {
            int ixj = t ^ j;
            if (ixj > t) {
                bool up = ((t & ks) == 0);
                int a = sb[t], c = sb[ixj];
                if ((a > c) == up) { sb[t] = c; sb[ixj] = a; }
            }
            __syncthreads();
        }
    }
    int num = min(m, MAXPTS);
    if (t < num) {
        int idx = sb[t];
        out[(s * MAXPTS + t) * 3 + 0] = pts[3 * idx + 0];
        out[(s * MAXPTS + t) * 3 + 1] = pts[3 * idx + 1];
        out[(s * MAXPTS + t) * 3 + 2] = pts[3 * idx + 2];
    }
}

// ---------------- launch ----------------
extern "C" void kernel_launch(void* const* d_in, const int* in_sizes, int n_in,
                              void* d_out, int out_size) {
    const float* pts = nullptr;
    const float* vs = nullptr;
    const float* cr = nullptr;
    int N = 0;
    for (int i = 0; i < n_in; i++) {
        if (in_sizes[i] == 3) vs = (const float*)d_in[i];
        else if (in_sizes[i] == 6) cr = (const float*)d_in[i];
        else { pts = (const float*)d_in[i]; N = in_sizes[i] / 3; }
    }
    float* out = (float*)d_out;

    cudaMemsetAsync(d_out, 0, (size_t)out_size * sizeof(float), 0);
    int rb = (M_MAX + 255) / 256;
    k_reset<<<rb, 256>>>();
    k_points<<<(N + 255) / 256, 256>>>(pts, vs, cr, N);
    k_hist<<<rb, 256>>>(vs, cr);
    k_thresh<<<1, 1>>>();
    k_collect<<<rb, 256>>>(vs, cr);
    k_sorttop<<<1, 1024>>>();
    k_prep<<<rb, 256>>>(vs, cr);
    k_startk<<<1, 1>>>();
    k_fps<<<NB, NT>>>(vs, cr);
    k_final<<<(MAXV + 255) / 256, 256>>>(vs, cr, out, out_size);
    k_cpts<<<(N + 255) / 256, 256>>>(N);
    k_emit<<<MAXV, CAP>>>(pts, out);
}